// round 15
// baseline (speedup 1.0000x reference)
#include <cuda_runtime.h>
#include <cuda_bf16.h>
#include <cstdint>

#define BB 32
#define NN 1024
#define TT 64

typedef unsigned long long ull;

// ---------------- scratch (device globals) -----------------------------------
// lhs/rhs hi/lo: tile-major pre-swizzled blocks, 16 KB per (b, tile128):
//   addr = (b*8+tile)*16384 + row*128 + (((chunk) ^ (row&7))*16) + inbyte
__device__ unsigned char g_lh_h[BB * NN * TT * 2];        // 4 MB
__device__ unsigned char g_lh_l[BB * NN * TT * 2];        // 4 MB
__device__ unsigned char g_rh_h[BB * NN * TT * 2];        // 4 MB
__device__ unsigned char g_rh_l[BB * NN * TT * 2];        // 4 MB
// int8 GEMM operand blocks: 16 KB = [h 8K][l 8K], swizzle chunk^(row&3)
__device__ __align__(128) unsigned char g_Vq[8 * 16 * 16384];                 // 2 MB
__device__ __align__(128) unsigned char g_Gq[(size_t)BB * 8 * 16 * 16384];    // 64 MB
__device__ float         g_bsT[NN * NN];                  // 4 MB
__device__ float         g_part[8][BB * NN];              // 1 MB
__device__ float         g_cinv[BB * NN];
__device__ unsigned int  g_vmax_u = 0u;                   // static init (idempotent)

// ---------------- helpers -----------------------------------------------------
__device__ __forceinline__ uint32_t smem_u32(const void* p) {
    uint32_t a;
    asm("{ .reg .u64 t; cvta.to.shared.u64 t, %1; cvt.u32.u64 %0, t; }"
        : "=r"(a) : "l"(p));
    return a;
}
__device__ __forceinline__ void bulk_g2s(uint32_t dst, const void* src,
                                         uint32_t bytes, uint32_t mbar) {
    asm volatile(
        "cp.async.bulk.shared::cluster.global.mbarrier::complete_tx::bytes "
        "[%0], [%1], %2, [%3];"
        :: "r"(dst), "l"(src), "r"(bytes), "r"(mbar) : "memory");
}
__device__ __forceinline__ void mbar_init(uint32_t a, uint32_t n) {
    asm volatile("mbarrier.init.shared.b64 [%0], %1;" :: "r"(a), "r"(n) : "memory");
}
__device__ __forceinline__ void mbar_expect(uint32_t a, uint32_t tx) {
    asm volatile("mbarrier.arrive.expect_tx.shared.b64 _, [%0], %1;"
                 :: "r"(a), "r"(tx) : "memory");
}
__device__ __forceinline__ void mbar_arrive(uint32_t a) {
    asm volatile("mbarrier.arrive.shared.b64 _, [%0];" :: "r"(a) : "memory");
}
#define MBAR_WAIT(mbar, parity) do {                                            \
    uint32_t _m = (mbar), _p = (parity), _done;                                 \
    asm volatile("{\n\t.reg .pred p;\n\t"                                       \
        "mbarrier.try_wait.parity.acquire.cta.shared::cta.b64 p, [%1], %2;\n\t" \
        "selp.b32 %0, 1, 0, p;\n\t}" : "=r"(_done) : "r"(_m), "r"(_p) : "memory"); \
    if (!_done) {                                                               \
        asm volatile("{\n\t.reg .pred P1;\n\t"                                  \
        "WAIT_LOOP_%=:\n\t"                                                     \
        "mbarrier.try_wait.parity.acquire.cta.shared::cta.b64 P1, [%0], %1;\n\t" \
        "@P1 bra.uni WAIT_DONE_%=;\n\tbra.uni WAIT_LOOP_%=;\n\tWAIT_DONE_%=:\n\t}" \
        :: "r"(_m), "r"(_p) : "memory");                                        \
    }                                                                           \
} while (0)

#define LDSM_X4(r0, r1, r2, r3, addr)                                           \
    asm volatile("ldmatrix.sync.aligned.m8n8.x4.shared.b16 {%0,%1,%2,%3}, [%4];" \
        : "=r"(r0), "=r"(r1), "=r"(r2), "=r"(r3) : "r"(addr))

__device__ __forceinline__ void mma16816(float* d, const uint32_t* a,
                                         uint32_t b0, uint32_t b1) {
    asm volatile(
        "mma.sync.aligned.m16n8k16.row.col.f32.bf16.bf16.f32 "
        "{%0,%1,%2,%3}, {%4,%5,%6,%7}, {%8,%9}, {%0,%1,%2,%3};"
        : "+f"(d[0]), "+f"(d[1]), "+f"(d[2]), "+f"(d[3])
        : "r"(a[0]), "r"(a[1]), "r"(a[2]), "r"(a[3]), "r"(b0), "r"(b1));
}
#define IMMA(d, a, b0, b1)                                                      \
    asm volatile(                                                               \
        "mma.sync.aligned.m16n8k32.row.col.s32.s8.u8.s32 "                      \
        "{%0,%1,%2,%3}, {%4,%5,%6,%7}, {%8,%9}, {%0,%1,%2,%3};"                 \
        : "+r"((d)[0]), "+r"((d)[1]), "+r"((d)[2]), "+r"((d)[3])                \
        : "r"((a)[0]), "r"((a)[1]), "r"((a)[2]), "r"((a)[3]), "r"(b0), "r"(b1))

// =============================================================================
// Kernel 1: prep — HBM-bound; writes bf16 hi/lo splits PRE-SWIZZLED tile-major
// =============================================================================
__global__ __launch_bounds__(64) void prep_kernel(
    const float* __restrict__ x, const float* __restrict__ W1,
    const float* __restrict__ W2, const float* __restrict__ W3)
{
    __shared__ float sx[64][65];
    __shared__ float l1[64];
    __shared__ float sW1[64], sW3[64];

    const int t = threadIdx.x;
    sW1[t] = W1[t];
    sW3[t] = W3[t];

    const float4* x4 = reinterpret_cast<const float4*>(x) + (size_t)blockIdx.x * 1024;
#pragma unroll
    for (int i = 0; i < 16; i++) {
        int idx = i * 64 + t;
        float4 v = x4[idx];
        int f = idx >> 4;
        int c = (idx & 15) * 4;
        sx[f][c + 0] = v.x; sx[f][c + 1] = v.y;
        sx[f][c + 2] = v.z; sx[f][c + 3] = v.w;
    }
    __syncthreads();

    float acc = 0.f;
#pragma unroll
    for (int k = 0; k < 64; k++) acc += sx[t][k] * sW1[k];
    l1[t] = acc;

    float r = 0.f;
#pragma unroll
    for (int f = 0; f < 64; f++) r += sW3[f] * sx[f][t];

    __syncthreads();

    float l = 0.f;
#pragma unroll
    for (int f = 0; f < 64; f++) l += l1[f] * W2[f * 64 + t];

    const int b = blockIdx.x >> 10;
    const int n = blockIdx.x & 1023;
    const int row = n & 127;
    size_t blk = ((size_t)(b * 8 + (n >> 7))) * 16384u;
    uint32_t off = row * 128 + ((((t >> 3)) ^ (row & 7)) * 16) + (t & 7) * 2;

    __nv_bfloat16 lh = __float2bfloat16(l);
    __nv_bfloat16 rh = __float2bfloat16(r);
    *(__nv_bfloat16*)&g_lh_h[blk + off] = lh;
    *(__nv_bfloat16*)&g_lh_l[blk + off] = __float2bfloat16(l - __bfloat162float(lh));
    *(__nv_bfloat16*)&g_rh_h[blk + off] = rh;
    *(__nv_bfloat16*)&g_rh_l[blk + off] = __float2bfloat16(r - __bfloat162float(rh));
}

// =============================================================================
// Kernel 2: Vmax (deterministic) + quantize Vs into tile-major swizzled blocks
// =============================================================================
__global__ __launch_bounds__(256) void vmax_kernel(const float* __restrict__ Vs)
{
    int i = (blockIdx.x * 256 + threadIdx.x) * 4;
    float4 v = *(const float4*)&Vs[i];
    float m = fmaxf(fmaxf(fabsf(v.x), fabsf(v.y)), fmaxf(fabsf(v.z), fabsf(v.w)));
#pragma unroll
    for (int s = 16; s > 0; s >>= 1)
        m = fmaxf(m, __shfl_xor_sync(0xffffffffu, m, s));
    if ((threadIdx.x & 31) == 0)
        atomicMax(&g_vmax_u, __float_as_uint(m));
}

__global__ __launch_bounds__(256) void quant_vs(const float* __restrict__ Vs)
{
    const float vmax = __uint_as_float(g_vmax_u);
    const float inv_s = 32639.f / fmaxf(vmax, 1e-30f);
    int e = (blockIdx.x * 256 + threadIdx.x) * 4;
    float4 v = *(const float4*)&Vs[e];
    uint32_t hp = 0, lp = 0;
    float vv[4] = {v.x, v.y, v.z, v.w};
#pragma unroll
    for (int j = 0; j < 4; j++) {
        int q = __float2int_rn(vv[j] * inv_s);
        q = max(-32768, min(32639, q));
        int vl = ((q + 128) & 255) - 128;
        int vh = (q - vl) >> 8;
        hp |= ((uint32_t)(vh & 255)) << (j * 8);
        lp |= ((uint32_t)(vl & 255)) << (j * 8);
    }
    int i = e >> 10;
    int k = e & 1023;
    int itile = i >> 7, row = i & 127;
    int kk = k >> 6, kc = k & 63;
    int c = kc >> 4, byt = kc & 15;
    uint32_t blk = (uint32_t)(itile * 16 + kk) * 16384u;
    uint32_t off = blk + row * 64 + (((c ^ (row & 3))) * 16) + byt;
    *(uint32_t*)&g_Vq[off] = hp;
    *(uint32_t*)&g_Vq[off + 8192] = lp;
}

// =============================================================================
// Kernel 2d: transpose bias once
// =============================================================================
__global__ __launch_bounds__(256) void transpose_bs(const float* __restrict__ bs)
{
    __shared__ float t[32][33];
    const int tx = threadIdx.x, ty = threadIdx.y;
    const int x0 = blockIdx.x * 32, y0 = blockIdx.y * 32;
#pragma unroll
    for (int r = 0; r < 4; r++)
        t[ty + r * 8][tx] = bs[(size_t)(y0 + ty + r * 8) * NN + x0 + tx];
    __syncthreads();
#pragma unroll
    for (int r = 0; r < 4; r++)
        g_bsT[(size_t)(x0 + ty + r * 8) * NN + y0 + tx] = t[tx][ty + r * 8];
}

// =============================================================================
// Kernel 3: product via bf16 mma. A resident + 4 B-tiles via bulk copies.
// Barrier-free consumer: per-slot full (tx) + empty (256-arrival) mbarriers;
// B refill overlaps the epilogue.
// =============================================================================
#define PM_SMEM 98304

__global__ void __launch_bounds__(256, 2) product_mma()
{
    extern __shared__ __align__(1024) char dsm[];
    __shared__ __align__(8) ull pm_mbars[5];   // [A][Bfull0][Bfull1][Bemp0][Bemp1]
    const uint32_t sm0 = smem_u32(dsm);
    const uint32_t mbA = smem_u32(pm_mbars);
    const uint32_t mbBF = mbA + 8;
    const uint32_t mbBE = mbA + 24;

    const int tid  = threadIdx.x;
    const int lane = tid & 31;
    const int w    = tid >> 5;
    const int b    = blockIdx.z;
    const int m0   = blockIdx.y * 128;
    const int mtile = blockIdx.y;
    const int ng0  = blockIdx.x * 512;
    const int nt0  = blockIdx.x * 4;           // base ntile

    const int wi0 = (w >> 1) * 32;
    const int wm0 = (w & 1) * 64;

    const int a_row  = wi0 + (lane & 15);
    const int a_half = lane >> 4;
    const int b_nB   = (lane & 7) + ((lane >> 4) << 3);
    const int b_half = (lane >> 3) & 1;
    const int swz    = lane & 7;

    if (tid == 0) {
        mbar_init(mbA, 1);
        mbar_init(mbBF, 1);
        mbar_init(mbBF + 8, 1);
        mbar_init(mbBE, 256);
        mbar_init(mbBE + 8, 256);
    }
    __syncthreads();

    auto issue_B = [&](int t) {
        uint32_t mb = mbBF + (t & 1) * 8;
        uint32_t sb = sm0 + 32768 + (t & 1) * 32768;
        size_t blk = ((size_t)(b * 8 + nt0 + t)) * 16384u;
        mbar_expect(mb, 32768);
        bulk_g2s(sb,         g_lh_h + blk, 16384, mb);
        bulk_g2s(sb + 16384, g_lh_l + blk, 16384, mb);
    };

    if (tid == 0) {
        size_t ablk = ((size_t)(b * 8 + mtile)) * 16384u;
        mbar_expect(mbA, 32768);
        bulk_g2s(sm0,         g_rh_h + ablk, 16384, mbA);
        bulk_g2s(sm0 + 16384, g_rh_l + ablk, 16384, mbA);
        issue_B(0);
        issue_B(1);
    }

#pragma unroll 1
    for (int t = 0; t < 4; t++) {
        const int slot = t & 1;
        const int ph = (t >> 1) & 1;
        if (t == 0) MBAR_WAIT(mbA, 0);
        MBAR_WAIT(mbBF + slot * 8, ph);

        const uint32_t sbB = sm0 + 32768 + slot * 32768;

        float acc[2][8][4];
#pragma unroll
        for (int mt = 0; mt < 2; mt++)
#pragma unroll
            for (int j = 0; j < 8; j++)
#pragma unroll
                for (int q = 0; q < 4; q++) acc[mt][j][q] = 0.f;

#pragma unroll
        for (int ks = 0; ks < 4; ks++) {
            uint32_t ah[2][4], al[2][4];
#pragma unroll
            for (int mt = 0; mt < 2; mt++) {
                uint32_t off = (a_row + mt * 16) * 128 + (((2 * ks + a_half) ^ swz) * 16);
                LDSM_X4(ah[mt][0], ah[mt][1], ah[mt][2], ah[mt][3], sm0 + off);
                LDSM_X4(al[mt][0], al[mt][1], al[mt][2], al[mt][3], sm0 + 16384 + off);
            }
#pragma unroll
            for (int nt = 0; nt < 4; nt++) {
                uint32_t bh[4], bl[4];
                uint32_t off = (wm0 + nt * 16 + b_nB) * 128 + (((2 * ks + b_half) ^ swz) * 16);
                LDSM_X4(bh[0], bh[1], bh[2], bh[3], sbB + off);
                LDSM_X4(bl[0], bl[1], bl[2], bl[3], sbB + 16384 + off);
#pragma unroll
                for (int mt = 0; mt < 2; mt++) {
                    mma16816(acc[mt][nt * 2 + 0], ah[mt], bh[0], bh[1]);
                    mma16816(acc[mt][nt * 2 + 1], ah[mt], bh[2], bh[3]);
                    mma16816(acc[mt][nt * 2 + 0], ah[mt], bl[0], bl[1]);
                    mma16816(acc[mt][nt * 2 + 1], ah[mt], bl[2], bl[3]);
                    mma16816(acc[mt][nt * 2 + 0], al[mt], bh[0], bh[1]);
                    mma16816(acc[mt][nt * 2 + 1], al[mt], bh[2], bh[3]);
                }
            }
        }

        // all B-slot reads done — release slot; tid0 refills while we epilogue
        mbar_arrive(mbBE + slot * 8);
        if (tid == 0 && t + 2 < 4) {
            MBAR_WAIT(mbBE + slot * 8, ph);
            issue_B(t + 2);
        }

        // epilogue: sigmoid, 16-bit quantize, write into swizzled Gq
        const int n0t = ng0 + t * 128;
#pragma unroll
        for (int mt = 0; mt < 2; mt++) {
            int r0 = m0 + wi0 + mt * 16 + (lane >> 2);
#pragma unroll
            for (int nt = 0; nt < 4; nt++)
#pragma unroll
                for (int h = 0; h < 2; h++) {
                    int j = nt * 2 + h;
                    int cn = n0t + wm0 + nt * 16 + h * 8 + (lane & 3) * 2;
                    int kk = cn >> 6, kc = cn & 63;
                    int c = kc >> 4, byt = kc & 15;
#pragma unroll
                    for (int rr = 0; rr < 2; rr++) {
                        int row = r0 + rr * 8;
                        int rowt = row & 127;
                        float p0 = acc[mt][j][rr * 2 + 0];
                        float p1 = acc[mt][j][rr * 2 + 1];
                        float2 bb = *(const float2*)&g_bsT[(size_t)row * NN + cn];
                        float g0 = 1.f / (1.f + __expf(-(p0 + bb.x)));
                        float g1 = 1.f / (1.f + __expf(-(p1 + bb.y)));
                        uint32_t q0 = __float2uint_rn(g0 * 65535.f);
                        uint32_t q1 = __float2uint_rn(g1 * 65535.f);
                        size_t blk = ((size_t)((b * 8 + mtile) * 16 + kk)) * 16384u;
                        size_t off = blk + rowt * 64 + (((c ^ (rowt & 3))) * 16) + byt;
                        *(unsigned short*)&g_Gq[off] =
                            (unsigned short)((q0 >> 8) | ((q1 >> 8) << 8));
                        *(unsigned short*)&g_Gq[off + 8192] =
                            (unsigned short)((q0 & 255) | ((q1 & 255) << 8));
                    }
                }
        }
    }
}

// =============================================================================
// Kernel 4: int8 tensor-core GEMM (256 threads, warp tile 32x64), bulk-copy
// producer, 5-stage ring, barrier-free (full tx + empty 256-arrival mbarriers).
// =============================================================================
#define GI_STAGE_BYTES 32768
#define GI_STAGES 5
#define GI_SMEM (GI_STAGES * GI_STAGE_BYTES)   // 160 KB

__global__ void __launch_bounds__(256, 1) gemm_i8(float* __restrict__ S)
{
    extern __shared__ __align__(1024) char dsm[];
    __shared__ __align__(8) ull mbars[2 * GI_STAGES];    // [full x5][empty x5]
    __shared__ float wsum[8][64];
    const uint32_t sm0 = smem_u32(dsm);
    const uint32_t mbF = smem_u32(mbars);
    const uint32_t mbE = mbF + GI_STAGES * 8;

    const int tid  = threadIdx.x;
    const int lane = tid & 31;
    const int w    = tid >> 5;
    const int b    = blockIdx.z;
    const int itile = blockIdx.y;
    const int mtile = blockIdx.x;
    const int i0g  = itile * 128;
    const int m0   = mtile * 128;

    const int wi0 = (w >> 1) * 32;
    const int wm0 = (w & 1) * 64;

    const int a_row  = wi0 + (lane & 15);
    const int a_half = lane >> 4;
    const int aswz   = a_row & 3;
    const int b_nB   = (lane & 7) + ((lane >> 4) << 3);
    const int b_half = (lane >> 3) & 1;
    const int bswz   = b_nB & 3;

    if (tid == 0) {
#pragma unroll
        for (int s = 0; s < GI_STAGES; s++) {
            mbar_init(mbF + s * 8, 1);
            mbar_init(mbE + s * 8, 256);
        }
    }
    __syncthreads();

    const unsigned char* srcA0 = g_Vq + (size_t)(itile * 16) * 16384u;
    const unsigned char* srcB0 = g_Gq + (size_t)((b * 8 + mtile) * 16) * 16384u;

    auto issue = [&](int kk, int s) {
        uint32_t mb = mbF + s * 8;
        uint32_t sb = sm0 + s * GI_STAGE_BYTES;
        mbar_expect(mb, 32768);
        bulk_g2s(sb,         srcA0 + (size_t)kk * 16384u, 16384, mb);
        bulk_g2s(sb + 16384, srcB0 + (size_t)kk * 16384u, 16384, mb);
    };

    if (tid == 0) {
#pragma unroll
        for (int k = 0; k < GI_STAGES; k++) issue(k, k);
    }

    int acc1[2][8][4], acc2[2][8][4];
#pragma unroll
    for (int mt = 0; mt < 2; mt++)
#pragma unroll
        for (int j = 0; j < 8; j++)
#pragma unroll
            for (int q = 0; q < 4; q++) { acc1[mt][j][q] = 0; acc2[mt][j][q] = 0; }

    int s = 0, p = 0;
#pragma unroll 1
    for (int kk = 0; kk < 16; kk++) {
        MBAR_WAIT(mbF + s * 8, p);

        const uint32_t sb = sm0 + s * GI_STAGE_BYTES;

#pragma unroll
        for (int ks = 0; ks < 2; ks++) {
            uint32_t ah[2][4], al[2][4];
#pragma unroll
            for (int mt = 0; mt < 2; mt++) {
                uint32_t off = (a_row + mt * 16) * 64
                             + (((2 * ks + a_half) ^ aswz) * 16);
                LDSM_X4(ah[mt][0], ah[mt][1], ah[mt][2], ah[mt][3], sb + off);
                LDSM_X4(al[mt][0], al[mt][1], al[mt][2], al[mt][3], sb + 8192 + off);
            }
            uint32_t bh[4][4], bl[4][4];
#pragma unroll
            for (int nt = 0; nt < 4; nt++) {
                uint32_t off = (wm0 + nt * 16 + b_nB) * 64
                             + (((2 * ks + b_half) ^ bswz) * 16);
                LDSM_X4(bh[nt][0], bh[nt][1], bh[nt][2], bh[nt][3], sb + 16384 + off);
                LDSM_X4(bl[nt][0], bl[nt][1], bl[nt][2], bl[nt][3], sb + 24576 + off);
            }
            // term-grouped issue (max RAW spacing on acc2)
#pragma unroll
            for (int mt = 0; mt < 2; mt++)
#pragma unroll
                for (int nt = 0; nt < 4; nt++) {
                    IMMA(acc1[mt][nt * 2 + 0], ah[mt], bh[nt][0], bh[nt][1]);
                    IMMA(acc1[mt][nt * 2 + 1], ah[mt], bh[nt][2], bh[nt][3]);
                }
#pragma unroll
            for (int mt = 0; mt < 2; mt++)
#pragma unroll
                for (int nt = 0; nt < 4; nt++) {
                    IMMA(acc2[mt][nt * 2 + 0], ah[mt], bl[nt][0], bl[nt][1]);
                    IMMA(acc2[mt][nt * 2 + 1], ah[mt], bl[nt][2], bl[nt][3]);
                }
#pragma unroll
            for (int mt = 0; mt < 2; mt++)
#pragma unroll
                for (int nt = 0; nt < 4; nt++) {
                    IMMA(acc2[mt][nt * 2 + 0], al[mt], bh[nt][0], bh[nt][1]);
                    IMMA(acc2[mt][nt * 2 + 1], al[mt], bh[nt][2], bh[nt][3]);
                }
        }

        // stage kk fully consumed (LDSM is synchronous)
        mbar_arrive(mbE + s * 8);
        if (tid == 0 && kk + GI_STAGES < 16) {
            MBAR_WAIT(mbE + s * 8, p);   // all 256 released this slot's phase
            issue(kk + GI_STAGES, s);
        }
        if (++s == GI_STAGES) { s = 0; p ^= 1; }
    }

    // epilogue: S = sc1*acc1 + sc2*acc2; write exp(S) + column partials
    const float s_scale = __uint_as_float(g_vmax_u) * (1.f / 32639.f);
    const float base = s_scale * (1.f / 65535.f);
    const float sc1 = base * 65536.f;
    const float sc2 = base * 256.f;

    float cs[16];
#pragma unroll
    for (int i = 0; i < 16; i++) cs[i] = 0.f;

    float* Sb = S + ((size_t)b << 20);
#pragma unroll
    for (int mt = 0; mt < 2; mt++) {
        int r0 = i0g + wi0 + mt * 16 + (lane >> 2);
#pragma unroll
        for (int nt = 0; nt < 4; nt++)
#pragma unroll
            for (int h = 0; h < 2; h++) {
                int j = nt * 2 + h;
                int cm = m0 + wm0 + nt * 16 + h * 8 + (lane & 3) * 2;
                float v0 = fmaf(sc1, (float)acc1[mt][j][0], sc2 * (float)acc2[mt][j][0]);
                float v1 = fmaf(sc1, (float)acc1[mt][j][1], sc2 * (float)acc2[mt][j][1]);
                float v2 = fmaf(sc1, (float)acc1[mt][j][2], sc2 * (float)acc2[mt][j][2]);
                float v3 = fmaf(sc1, (float)acc1[mt][j][3], sc2 * (float)acc2[mt][j][3]);
                float e0 = __expf(v0), e1 = __expf(v1);
                float e2 = __expf(v2), e3 = __expf(v3);
                *(float2*)&Sb[((size_t)r0 << 10) + cm] = make_float2(e0, e1);
                *(float2*)&Sb[((size_t)(r0 + 8) << 10) + cm] = make_float2(e2, e3);
                cs[nt * 4 + h * 2 + 0] += e0 + e2;
                cs[nt * 4 + h * 2 + 1] += e1 + e3;
            }
    }
#pragma unroll
    for (int i = 0; i < 16; i++) {
        cs[i] += __shfl_xor_sync(0xffffffffu, cs[i], 4);
        cs[i] += __shfl_xor_sync(0xffffffffu, cs[i], 8);
        cs[i] += __shfl_xor_sync(0xffffffffu, cs[i], 16);
    }
    if (lane < 4) {
#pragma unroll
        for (int nt = 0; nt < 4; nt++)
#pragma unroll
            for (int h = 0; h < 2; h++) {
                wsum[w][nt * 16 + h * 8 + lane * 2 + 0] = cs[nt * 4 + h * 2 + 0];
                wsum[w][nt * 16 + h * 8 + lane * 2 + 1] = cs[nt * 4 + h * 2 + 1];
            }
    }
    __syncthreads();
    if (tid < 128) {
        int h = tid >> 6, c = tid & 63;
        float sum = wsum[h][c] + wsum[2 + h][c] + wsum[4 + h][c] + wsum[6 + h][c];
        g_part[itile][((size_t)b << 10) + m0 + h * 64 + c] = sum;
    }
}

// =============================================================================
// Kernel 5: reduce per-i-tile partials -> 1/colsum
// =============================================================================
__global__ __launch_bounds__(256) void reduce_part()
{
    int t = blockIdx.x * 256 + threadIdx.x;
    float s = 0.f;
#pragma unroll
    for (int q = 0; q < 8; q++) s += g_part[q][t];
    g_cinv[t] = __fdividef(1.f, s);
}

// =============================================================================
// Kernel 6: normalize in place: out = expS * (1/colsum)
// =============================================================================
__global__ __launch_bounds__(256) void normalize_kernel(float* __restrict__ S)
{
    const int bi = blockIdx.x;
    const int b = bi >> 10;
    const int m = threadIdx.x * 4;
    size_t base = (size_t)bi * NN + m;

    float4 v  = *(const float4*)&S[base];
    float4 iv = *(const float4*)&g_cinv[b * NN + m];
    float4 o;
    o.x = v.x * iv.x;
    o.y = v.y * iv.y;
    o.z = v.z * iv.z;
    o.w = v.w * iv.w;
    *(float4*)&S[base] = o;
}

// =============================================================================
extern "C" void kernel_launch(void* const* d_in, const int* in_sizes, int n_in,
                              void* d_out, int out_size)
{
    (void)in_sizes; (void)n_in; (void)out_size;
    const float* x  = (const float*)d_in[0];
    const float* W1 = (const float*)d_in[1];
    const float* W2 = (const float*)d_in[2];
    const float* W3 = (const float*)d_in[3];
    const float* bs = (const float*)d_in[4];
    const float* Vs = (const float*)d_in[5];
    float* out = (float*)d_out;

    cudaFuncSetAttribute(product_mma, cudaFuncAttributeMaxDynamicSharedMemorySize,
                         PM_SMEM);
    cudaFuncSetAttribute(gemm_i8, cudaFuncAttributeMaxDynamicSharedMemorySize,
                         GI_SMEM);

    prep_kernel<<<BB * NN, 64>>>(x, W1, W2, W3);
    vmax_kernel<<<NN * NN / 1024, 256>>>(Vs);
    quant_vs<<<NN * NN / 1024, 256>>>(Vs);
    transpose_bs<<<dim3(32, 32), dim3(32, 8)>>>(bs);
    product_mma<<<dim3(2, 8, BB), 256, PM_SMEM>>>();
    gemm_i8<<<dim3(8, 8, BB), 256, GI_SMEM>>>(out);
    reduce_part<<<128, 256>>>();
    normalize_kernel<<<BB * NN, 256>>>(out);
}

// round 16
// speedup vs baseline: 1.0211x; 1.0211x over previous
#include <cuda_runtime.h>
#include <cuda_bf16.h>
#include <cstdint>

#define BB 32
#define NN 1024
#define TT 64

typedef unsigned long long ull;

// ---------------- scratch (device globals) -----------------------------------
// lhs/rhs hi/lo: tile-major pre-swizzled blocks, 16 KB per (b, tile128):
//   addr = (b*8+tile)*16384 + row*128 + (((chunk) ^ (row&7))*16) + inbyte
__device__ unsigned char g_lh_h[BB * NN * TT * 2];        // 4 MB
__device__ unsigned char g_lh_l[BB * NN * TT * 2];        // 4 MB
__device__ unsigned char g_rh_h[BB * NN * TT * 2];        // 4 MB
__device__ unsigned char g_rh_l[BB * NN * TT * 2];        // 4 MB
// int8 GEMM operand blocks: 16 KB = [h 8K][l 8K], swizzle chunk^(row&3)
__device__ __align__(128) unsigned char g_Vq[8 * 16 * 16384];                 // 2 MB
__device__ __align__(128) unsigned char g_Gq[(size_t)BB * 8 * 16 * 16384];    // 64 MB
__device__ float         g_bsT[NN * NN];                  // 4 MB
__device__ float         g_part[8][BB * NN];              // 1 MB
__device__ float         g_cinv[BB * NN];
__device__ unsigned int  g_vmax_u = 0u;                   // static init (idempotent)

// ---------------- helpers -----------------------------------------------------
__device__ __forceinline__ uint32_t smem_u32(const void* p) {
    uint32_t a;
    asm("{ .reg .u64 t; cvta.to.shared.u64 t, %1; cvt.u32.u64 %0, t; }"
        : "=r"(a) : "l"(p));
    return a;
}
__device__ __forceinline__ void bulk_g2s(uint32_t dst, const void* src,
                                         uint32_t bytes, uint32_t mbar) {
    asm volatile(
        "cp.async.bulk.shared::cluster.global.mbarrier::complete_tx::bytes "
        "[%0], [%1], %2, [%3];"
        :: "r"(dst), "l"(src), "r"(bytes), "r"(mbar) : "memory");
}
__device__ __forceinline__ void mbar_init(uint32_t a, uint32_t n) {
    asm volatile("mbarrier.init.shared.b64 [%0], %1;" :: "r"(a), "r"(n) : "memory");
}
__device__ __forceinline__ void mbar_expect(uint32_t a, uint32_t tx) {
    asm volatile("mbarrier.arrive.expect_tx.shared.b64 _, [%0], %1;"
                 :: "r"(a), "r"(tx) : "memory");
}
__device__ __forceinline__ void mbar_arrive(uint32_t a) {
    asm volatile("mbarrier.arrive.shared.b64 _, [%0];" :: "r"(a) : "memory");
}
#define MBAR_WAIT(mbar, parity) do {                                            \
    uint32_t _m = (mbar), _p = (parity), _done;                                 \
    asm volatile("{\n\t.reg .pred p;\n\t"                                       \
        "mbarrier.try_wait.parity.acquire.cta.shared::cta.b64 p, [%1], %2;\n\t" \
        "selp.b32 %0, 1, 0, p;\n\t}" : "=r"(_done) : "r"(_m), "r"(_p) : "memory"); \
    if (!_done) {                                                               \
        asm volatile("{\n\t.reg .pred P1;\n\t"                                  \
        "WAIT_LOOP_%=:\n\t"                                                     \
        "mbarrier.try_wait.parity.acquire.cta.shared::cta.b64 P1, [%0], %1;\n\t" \
        "@P1 bra.uni WAIT_DONE_%=;\n\tbra.uni WAIT_LOOP_%=;\n\tWAIT_DONE_%=:\n\t}" \
        :: "r"(_m), "r"(_p) : "memory");                                        \
    }                                                                           \
} while (0)

#define LDSM_X4(r0, r1, r2, r3, addr)                                           \
    asm volatile("ldmatrix.sync.aligned.m8n8.x4.shared.b16 {%0,%1,%2,%3}, [%4];" \
        : "=r"(r0), "=r"(r1), "=r"(r2), "=r"(r3) : "r"(addr))

__device__ __forceinline__ void mma16816(float* d, const uint32_t* a,
                                         uint32_t b0, uint32_t b1) {
    asm volatile(
        "mma.sync.aligned.m16n8k16.row.col.f32.bf16.bf16.f32 "
        "{%0,%1,%2,%3}, {%4,%5,%6,%7}, {%8,%9}, {%0,%1,%2,%3};"
        : "+f"(d[0]), "+f"(d[1]), "+f"(d[2]), "+f"(d[3])
        : "r"(a[0]), "r"(a[1]), "r"(a[2]), "r"(a[3]), "r"(b0), "r"(b1));
}
#define IMMA(d, a, b0, b1)                                                      \
    asm volatile(                                                               \
        "mma.sync.aligned.m16n8k32.row.col.s32.s8.u8.s32 "                      \
        "{%0,%1,%2,%3}, {%4,%5,%6,%7}, {%8,%9}, {%0,%1,%2,%3};"                 \
        : "+r"((d)[0]), "+r"((d)[1]), "+r"((d)[2]), "+r"((d)[3])                \
        : "r"((a)[0]), "r"((a)[1]), "r"((a)[2]), "r"((a)[3]), "r"(b0), "r"(b1))

// =============================================================================
// Kernel 1: prep — HBM-bound; writes bf16 hi/lo splits PRE-SWIZZLED tile-major
// =============================================================================
__global__ __launch_bounds__(64) void prep_kernel(
    const float* __restrict__ x, const float* __restrict__ W1,
    const float* __restrict__ W2, const float* __restrict__ W3)
{
    __shared__ float sx[64][65];
    __shared__ float l1[64];
    __shared__ float sW1[64], sW3[64];

    const int t = threadIdx.x;
    sW1[t] = W1[t];
    sW3[t] = W3[t];

    const float4* x4 = reinterpret_cast<const float4*>(x) + (size_t)blockIdx.x * 1024;
#pragma unroll
    for (int i = 0; i < 16; i++) {
        int idx = i * 64 + t;
        float4 v = x4[idx];
        int f = idx >> 4;
        int c = (idx & 15) * 4;
        sx[f][c + 0] = v.x; sx[f][c + 1] = v.y;
        sx[f][c + 2] = v.z; sx[f][c + 3] = v.w;
    }
    __syncthreads();

    float acc = 0.f;
#pragma unroll
    for (int k = 0; k < 64; k++) acc += sx[t][k] * sW1[k];
    l1[t] = acc;

    float r = 0.f;
#pragma unroll
    for (int f = 0; f < 64; f++) r += sW3[f] * sx[f][t];

    __syncthreads();

    float l = 0.f;
#pragma unroll
    for (int f = 0; f < 64; f++) l += l1[f] * W2[f * 64 + t];

    const int b = blockIdx.x >> 10;
    const int n = blockIdx.x & 1023;
    const int row = n & 127;
    size_t blk = ((size_t)(b * 8 + (n >> 7))) * 16384u;
    uint32_t off = row * 128 + ((((t >> 3)) ^ (row & 7)) * 16) + (t & 7) * 2;

    __nv_bfloat16 lh = __float2bfloat16(l);
    __nv_bfloat16 rh = __float2bfloat16(r);
    *(__nv_bfloat16*)&g_lh_h[blk + off] = lh;
    *(__nv_bfloat16*)&g_lh_l[blk + off] = __float2bfloat16(l - __bfloat162float(lh));
    *(__nv_bfloat16*)&g_rh_h[blk + off] = rh;
    *(__nv_bfloat16*)&g_rh_l[blk + off] = __float2bfloat16(r - __bfloat162float(rh));
}

// =============================================================================
// Kernel 2: Vmax (deterministic) + quantize Vs into tile-major swizzled blocks
// =============================================================================
__global__ __launch_bounds__(256) void vmax_kernel(const float* __restrict__ Vs)
{
    int i = (blockIdx.x * 256 + threadIdx.x) * 4;
    float4 v = *(const float4*)&Vs[i];
    float m = fmaxf(fmaxf(fabsf(v.x), fabsf(v.y)), fmaxf(fabsf(v.z), fabsf(v.w)));
#pragma unroll
    for (int s = 16; s > 0; s >>= 1)
        m = fmaxf(m, __shfl_xor_sync(0xffffffffu, m, s));
    if ((threadIdx.x & 31) == 0)
        atomicMax(&g_vmax_u, __float_as_uint(m));
}

__global__ __launch_bounds__(256) void quant_vs(const float* __restrict__ Vs)
{
    const float vmax = __uint_as_float(g_vmax_u);
    const float inv_s = 32639.f / fmaxf(vmax, 1e-30f);
    int e = (blockIdx.x * 256 + threadIdx.x) * 4;
    float4 v = *(const float4*)&Vs[e];
    uint32_t hp = 0, lp = 0;
    float vv[4] = {v.x, v.y, v.z, v.w};
#pragma unroll
    for (int j = 0; j < 4; j++) {
        int q = __float2int_rn(vv[j] * inv_s);
        q = max(-32768, min(32639, q));
        int vl = ((q + 128) & 255) - 128;
        int vh = (q - vl) >> 8;
        hp |= ((uint32_t)(vh & 255)) << (j * 8);
        lp |= ((uint32_t)(vl & 255)) << (j * 8);
    }
    int i = e >> 10;
    int k = e & 1023;
    int itile = i >> 7, row = i & 127;
    int kk = k >> 6, kc = k & 63;
    int c = kc >> 4, byt = kc & 15;
    uint32_t blk = (uint32_t)(itile * 16 + kk) * 16384u;
    uint32_t off = blk + row * 64 + (((c ^ (row & 3))) * 16) + byt;
    *(uint32_t*)&g_Vq[off] = hp;
    *(uint32_t*)&g_Vq[off + 8192] = lp;
}

// =============================================================================
// Kernel 2d: transpose bias once
// =============================================================================
__global__ __launch_bounds__(256) void transpose_bs(const float* __restrict__ bs)
{
    __shared__ float t[32][33];
    const int tx = threadIdx.x, ty = threadIdx.y;
    const int x0 = blockIdx.x * 32, y0 = blockIdx.y * 32;
#pragma unroll
    for (int r = 0; r < 4; r++)
        t[ty + r * 8][tx] = bs[(size_t)(y0 + ty + r * 8) * NN + x0 + tx];
    __syncthreads();
#pragma unroll
    for (int r = 0; r < 4; r++)
        g_bsT[(size_t)(x0 + ty + r * 8) * NN + y0 + tx] = t[tx][ty + r * 8];
}

// =============================================================================
// Kernel 3: product via bf16 mma. A resident + 4 B-tiles via bulk copies.
// R14 structure, ONE change: B refill issued right after the post-MMA sync,
// BEFORE the epilogue, so the copy hides under the epilogue.
// =============================================================================
#define PM_SMEM 98304

__global__ void __launch_bounds__(256, 2) product_mma()
{
    extern __shared__ __align__(1024) char dsm[];
    __shared__ __align__(8) ull pm_mbars[3];   // [A][Bslot0][Bslot1]
    const uint32_t sm0 = smem_u32(dsm);
    const uint32_t mbA = smem_u32(pm_mbars);

    const int tid  = threadIdx.x;
    const int lane = tid & 31;
    const int w    = tid >> 5;
    const int b    = blockIdx.z;
    const int m0   = blockIdx.y * 128;
    const int mtile = blockIdx.y;
    const int ng0  = blockIdx.x * 512;
    const int nt0  = blockIdx.x * 4;           // base ntile

    const int wi0 = (w >> 1) * 32;
    const int wm0 = (w & 1) * 64;

    const int a_row  = wi0 + (lane & 15);
    const int a_half = lane >> 4;
    const int b_nB   = (lane & 7) + ((lane >> 4) << 3);
    const int b_half = (lane >> 3) & 1;
    const int swz    = lane & 7;

    if (tid == 0) {
        mbar_init(mbA, 1);
        mbar_init(mbA + 8, 1);
        mbar_init(mbA + 16, 1);
    }
    __syncthreads();

    auto issue_B = [&](int t) {
        uint32_t mb = mbA + 8 + (t & 1) * 8;
        uint32_t sb = sm0 + 32768 + (t & 1) * 32768;
        size_t blk = ((size_t)(b * 8 + nt0 + t)) * 16384u;
        mbar_expect(mb, 32768);
        bulk_g2s(sb,         g_lh_h + blk, 16384, mb);
        bulk_g2s(sb + 16384, g_lh_l + blk, 16384, mb);
    };

    if (tid == 0) {
        size_t ablk = ((size_t)(b * 8 + mtile)) * 16384u;
        mbar_expect(mbA, 32768);
        bulk_g2s(sm0,         g_rh_h + ablk, 16384, mbA);
        bulk_g2s(sm0 + 16384, g_rh_l + ablk, 16384, mbA);
        issue_B(0);
        issue_B(1);
    }

#pragma unroll 1
    for (int t = 0; t < 4; t++) {
        if (t == 0) MBAR_WAIT(mbA, 0);
        MBAR_WAIT(mbA + 8 + (t & 1) * 8, (t >> 1) & 1);

        const uint32_t sbB = sm0 + 32768 + (t & 1) * 32768;

        float acc[2][8][4];
#pragma unroll
        for (int mt = 0; mt < 2; mt++)
#pragma unroll
            for (int j = 0; j < 8; j++)
#pragma unroll
                for (int q = 0; q < 4; q++) acc[mt][j][q] = 0.f;

#pragma unroll
        for (int ks = 0; ks < 4; ks++) {
            uint32_t ah[2][4], al[2][4];
#pragma unroll
            for (int mt = 0; mt < 2; mt++) {
                uint32_t off = (a_row + mt * 16) * 128 + (((2 * ks + a_half) ^ swz) * 16);
                LDSM_X4(ah[mt][0], ah[mt][1], ah[mt][2], ah[mt][3], sm0 + off);
                LDSM_X4(al[mt][0], al[mt][1], al[mt][2], al[mt][3], sm0 + 16384 + off);
            }
#pragma unroll
            for (int nt = 0; nt < 4; nt++) {
                uint32_t bh[4], bl[4];
                uint32_t off = (wm0 + nt * 16 + b_nB) * 128 + (((2 * ks + b_half) ^ swz) * 16);
                LDSM_X4(bh[0], bh[1], bh[2], bh[3], sbB + off);
                LDSM_X4(bl[0], bl[1], bl[2], bl[3], sbB + 16384 + off);
#pragma unroll
                for (int mt = 0; mt < 2; mt++) {
                    mma16816(acc[mt][nt * 2 + 0], ah[mt], bh[0], bh[1]);
                    mma16816(acc[mt][nt * 2 + 1], ah[mt], bh[2], bh[3]);
                    mma16816(acc[mt][nt * 2 + 0], ah[mt], bl[0], bl[1]);
                    mma16816(acc[mt][nt * 2 + 1], ah[mt], bl[2], bl[3]);
                    mma16816(acc[mt][nt * 2 + 0], al[mt], bh[0], bh[1]);
                    mma16816(acc[mt][nt * 2 + 1], al[mt], bh[2], bh[3]);
                }
            }
        }

        // all warps done reading slot (t&1) -> refill it NOW, epilogue after
        __syncthreads();
        if (tid == 0 && t + 2 < 4) issue_B(t + 2);

        // epilogue: sigmoid, 16-bit quantize, write into swizzled Gq
        const int n0t = ng0 + t * 128;
#pragma unroll
        for (int mt = 0; mt < 2; mt++) {
            int r0 = m0 + wi0 + mt * 16 + (lane >> 2);
#pragma unroll
            for (int nt = 0; nt < 4; nt++)
#pragma unroll
                for (int h = 0; h < 2; h++) {
                    int j = nt * 2 + h;
                    int cn = n0t + wm0 + nt * 16 + h * 8 + (lane & 3) * 2;
                    int kk = cn >> 6, kc = cn & 63;
                    int c = kc >> 4, byt = kc & 15;
#pragma unroll
                    for (int rr = 0; rr < 2; rr++) {
                        int row = r0 + rr * 8;
                        int rowt = row & 127;
                        float p0 = acc[mt][j][rr * 2 + 0];
                        float p1 = acc[mt][j][rr * 2 + 1];
                        float2 bb = *(const float2*)&g_bsT[(size_t)row * NN + cn];
                        float g0 = 1.f / (1.f + __expf(-(p0 + bb.x)));
                        float g1 = 1.f / (1.f + __expf(-(p1 + bb.y)));
                        uint32_t q0 = __float2uint_rn(g0 * 65535.f);
                        uint32_t q1 = __float2uint_rn(g1 * 65535.f);
                        size_t blk = ((size_t)((b * 8 + mtile) * 16 + kk)) * 16384u;
                        size_t off = blk + rowt * 64 + (((c ^ (rowt & 3))) * 16) + byt;
                        *(unsigned short*)&g_Gq[off] =
                            (unsigned short)((q0 >> 8) | ((q1 >> 8) << 8));
                        *(unsigned short*)&g_Gq[off + 8192] =
                            (unsigned short)((q0 & 255) | ((q1 & 255) << 8));
                    }
                }
        }
    }
}

// =============================================================================
// Kernel 4: int8 tensor-core GEMM (256 threads, warp tile 32x64), bulk-copy
// producer, 4-stage ring, barrier-free (full tx + empty 256-arrival mbarriers).
// Byte-identical to the R14 (579.6 us) version.
// =============================================================================
#define GI_STAGE_BYTES 32768
#define GI_STAGES 4
#define GI_SMEM (GI_STAGES * GI_STAGE_BYTES)   // 128 KB

__global__ void __launch_bounds__(256, 1) gemm_i8(float* __restrict__ S)
{
    extern __shared__ __align__(1024) char dsm[];
    __shared__ __align__(8) ull mbars[2 * GI_STAGES];    // [full x4][empty x4]
    __shared__ float wsum[8][64];
    const uint32_t sm0 = smem_u32(dsm);
    const uint32_t mbF = smem_u32(mbars);
    const uint32_t mbE = mbF + GI_STAGES * 8;

    const int tid  = threadIdx.x;
    const int lane = tid & 31;
    const int w    = tid >> 5;
    const int b    = blockIdx.z;
    const int itile = blockIdx.y;
    const int mtile = blockIdx.x;
    const int i0g  = itile * 128;
    const int m0   = mtile * 128;

    const int wi0 = (w >> 1) * 32;
    const int wm0 = (w & 1) * 64;

    const int a_row  = wi0 + (lane & 15);
    const int a_half = lane >> 4;
    const int aswz   = a_row & 3;
    const int b_nB   = (lane & 7) + ((lane >> 4) << 3);
    const int b_half = (lane >> 3) & 1;
    const int bswz   = b_nB & 3;

    if (tid == 0) {
#pragma unroll
        for (int s = 0; s < GI_STAGES; s++) {
            mbar_init(mbF + s * 8, 1);
            mbar_init(mbE + s * 8, 256);
        }
    }
    __syncthreads();

    const unsigned char* srcA0 = g_Vq + (size_t)(itile * 16) * 16384u;
    const unsigned char* srcB0 = g_Gq + (size_t)((b * 8 + mtile) * 16) * 16384u;

    auto issue = [&](int kk) {
        int s = kk & 3;
        uint32_t mb = mbF + s * 8;
        uint32_t sb = sm0 + s * GI_STAGE_BYTES;
        mbar_expect(mb, 32768);
        bulk_g2s(sb,         srcA0 + (size_t)kk * 16384u, 16384, mb);
        bulk_g2s(sb + 16384, srcB0 + (size_t)kk * 16384u, 16384, mb);
    };

    if (tid == 0) {
#pragma unroll
        for (int k = 0; k < GI_STAGES; k++) issue(k);
    }

    int acc1[2][8][4], acc2[2][8][4];
#pragma unroll
    for (int mt = 0; mt < 2; mt++)
#pragma unroll
        for (int j = 0; j < 8; j++)
#pragma unroll
            for (int q = 0; q < 4; q++) { acc1[mt][j][q] = 0; acc2[mt][j][q] = 0; }

#pragma unroll 1
    for (int kk = 0; kk < 16; kk++) {
        const int s = kk & 3;
        const int ph = (kk >> 2) & 1;
        MBAR_WAIT(mbF + s * 8, ph);

        const uint32_t sb = sm0 + s * GI_STAGE_BYTES;

#pragma unroll
        for (int ks = 0; ks < 2; ks++) {
            uint32_t ah[2][4], al[2][4];
#pragma unroll
            for (int mt = 0; mt < 2; mt++) {
                uint32_t off = (a_row + mt * 16) * 64
                             + (((2 * ks + a_half) ^ aswz) * 16);
                LDSM_X4(ah[mt][0], ah[mt][1], ah[mt][2], ah[mt][3], sb + off);
                LDSM_X4(al[mt][0], al[mt][1], al[mt][2], al[mt][3], sb + 8192 + off);
            }
            uint32_t bh[4][4], bl[4][4];
#pragma unroll
            for (int nt = 0; nt < 4; nt++) {
                uint32_t off = (wm0 + nt * 16 + b_nB) * 64
                             + (((2 * ks + b_half) ^ bswz) * 16);
                LDSM_X4(bh[nt][0], bh[nt][1], bh[nt][2], bh[nt][3], sb + 16384 + off);
                LDSM_X4(bl[nt][0], bl[nt][1], bl[nt][2], bl[nt][3], sb + 24576 + off);
            }
            // term-grouped issue (max RAW spacing on acc2)
#pragma unroll
            for (int mt = 0; mt < 2; mt++)
#pragma unroll
                for (int nt = 0; nt < 4; nt++) {
                    IMMA(acc1[mt][nt * 2 + 0], ah[mt], bh[nt][0], bh[nt][1]);
                    IMMA(acc1[mt][nt * 2 + 1], ah[mt], bh[nt][2], bh[nt][3]);
                }
#pragma unroll
            for (int mt = 0; mt < 2; mt++)
#pragma unroll
                for (int nt = 0; nt < 4; nt++) {
                    IMMA(acc2[mt][nt * 2 + 0], ah[mt], bl[nt][0], bl[nt][1]);
                    IMMA(acc2[mt][nt * 2 + 1], ah[mt], bl[nt][2], bl[nt][3]);
                }
#pragma unroll
            for (int mt = 0; mt < 2; mt++)
#pragma unroll
                for (int nt = 0; nt < 4; nt++) {
                    IMMA(acc2[mt][nt * 2 + 0], al[mt], bh[nt][0], bh[nt][1]);
                    IMMA(acc2[mt][nt * 2 + 1], al[mt], bh[nt][2], bh[nt][3]);
                }
        }

        // all fragment reads for stage kk are complete (LDSM is synchronous)
        mbar_arrive(mbE + s * 8);
        if (tid == 0 && kk + GI_STAGES < 16) {
            MBAR_WAIT(mbE + s * 8, ph);   // all 256 consumed this slot's phase
            issue(kk + GI_STAGES);
        }
    }

    // epilogue: S = sc1*acc1 + sc2*acc2; write exp(S) + column partials
    const float s_scale = __uint_as_float(g_vmax_u) * (1.f / 32639.f);
    const float base = s_scale * (1.f / 65535.f);
    const float sc1 = base * 65536.f;
    const float sc2 = base * 256.f;

    float cs[16];
#pragma unroll
    for (int i = 0; i < 16; i++) cs[i] = 0.f;

    float* Sb = S + ((size_t)b << 20);
#pragma unroll
    for (int mt = 0; mt < 2; mt++) {
        int r0 = i0g + wi0 + mt * 16 + (lane >> 2);
#pragma unroll
        for (int nt = 0; nt < 4; nt++)
#pragma unroll
            for (int h = 0; h < 2; h++) {
                int j = nt * 2 + h;
                int cm = m0 + wm0 + nt * 16 + h * 8 + (lane & 3) * 2;
                float v0 = fmaf(sc1, (float)acc1[mt][j][0], sc2 * (float)acc2[mt][j][0]);
                float v1 = fmaf(sc1, (float)acc1[mt][j][1], sc2 * (float)acc2[mt][j][1]);
                float v2 = fmaf(sc1, (float)acc1[mt][j][2], sc2 * (float)acc2[mt][j][2]);
                float v3 = fmaf(sc1, (float)acc1[mt][j][3], sc2 * (float)acc2[mt][j][3]);
                float e0 = __expf(v0), e1 = __expf(v1);
                float e2 = __expf(v2), e3 = __expf(v3);
                *(float2*)&Sb[((size_t)r0 << 10) + cm] = make_float2(e0, e1);
                *(float2*)&Sb[((size_t)(r0 + 8) << 10) + cm] = make_float2(e2, e3);
                cs[nt * 4 + h * 2 + 0] += e0 + e2;
                cs[nt * 4 + h * 2 + 1] += e1 + e3;
            }
    }
#pragma unroll
    for (int i = 0; i < 16; i++) {
        cs[i] += __shfl_xor_sync(0xffffffffu, cs[i], 4);
        cs[i] += __shfl_xor_sync(0xffffffffu, cs[i], 8);
        cs[i] += __shfl_xor_sync(0xffffffffu, cs[i], 16);
    }
    if (lane < 4) {
#pragma unroll
        for (int nt = 0; nt < 4; nt++)
#pragma unroll
            for (int h = 0; h < 2; h++) {
                wsum[w][nt * 16 + h * 8 + lane * 2 + 0] = cs[nt * 4 + h * 2 + 0];
                wsum[w][nt * 16 + h * 8 + lane * 2 + 1] = cs[nt * 4 + h * 2 + 1];
            }
    }
    __syncthreads();
    if (tid < 128) {
        int h = tid >> 6, c = tid & 63;
        float sum = wsum[h][c] + wsum[2 + h][c] + wsum[4 + h][c] + wsum[6 + h][c];
        g_part[itile][((size_t)b << 10) + m0 + h * 64 + c] = sum;
    }
}

// =============================================================================
// Kernel 5: reduce per-i-tile partials -> 1/colsum
// =============================================================================
__global__ __launch_bounds__(256) void reduce_part()
{
    int t = blockIdx.x * 256 + threadIdx.x;
    float s = 0.f;
#pragma unroll
    for (int q = 0; q < 8; q++) s += g_part[q][t];
    g_cinv[t] = __fdividef(1.f, s);
}

// =============================================================================
// Kernel 6: normalize in place: out = expS * (1/colsum)
// =============================================================================
__global__ __launch_bounds__(256) void normalize_kernel(float* __restrict__ S)
{
    const int bi = blockIdx.x;
    const int b = bi >> 10;
    const int m = threadIdx.x * 4;
    size_t base = (size_t)bi * NN + m;

    float4 v  = *(const float4*)&S[base];
    float4 iv = *(const float4*)&g_cinv[b * NN + m];
    float4 o;
    o.x = v.x * iv.x;
    o.y = v.y * iv.y;
    o.z = v.z * iv.z;
    o.w = v.w * iv.w;
    *(float4*)&S[base] = o;
}

// =============================================================================
extern "C" void kernel_launch(void* const* d_in, const int* in_sizes, int n_in,
                              void* d_out, int out_size)
{
    (void)in_sizes; (void)n_in; (void)out_size;
    const float* x  = (const float*)d_in[0];
    const float* W1 = (const float*)d_in[1];
    const float* W2 = (const float*)d_in[2];
    const float* W3 = (const float*)d_in[3];
    const float* bs = (const float*)d_in[4];
    const float* Vs = (const float*)d_in[5];
    float* out = (float*)d_out;

    cudaFuncSetAttribute(product_mma, cudaFuncAttributeMaxDynamicSharedMemorySize,
                         PM_SMEM);
    cudaFuncSetAttribute(gemm_i8, cudaFuncAttributeMaxDynamicSharedMemorySize,
                         GI_SMEM);

    prep_kernel<<<BB * NN, 64>>>(x, W1, W2, W3);
    vmax_kernel<<<NN * NN / 1024, 256>>>(Vs);
    quant_vs<<<NN * NN / 1024, 256>>>(Vs);
    transpose_bs<<<dim3(32, 32), dim3(32, 8)>>>(bs);
    product_mma<<<dim3(2, 8, BB), 256, PM_SMEM>>>();
    gemm_i8<<<dim3(8, 8, BB), 256, GI_SMEM>>>(out);
    reduce_part<<<128, 256>>>();
    normalize_kernel<<<BB * NN, 256>>>(out);
}

// round 17
// speedup vs baseline: 1.0247x; 1.0035x over previous
#include <cuda_runtime.h>
#include <cuda_bf16.h>
#include <cstdint>

#define BB 32
#define NN 1024
#define TT 64

typedef unsigned long long ull;

// ---------------- scratch (device globals) -----------------------------------
// lhs/rhs hi/lo: tile-major pre-swizzled blocks, 16 KB per (b, tile128):
//   addr = (b*8+tile)*16384 + row*128 + (((chunk) ^ (row&7))*16) + inbyte
__device__ unsigned char g_lh_h[BB * NN * TT * 2];        // 4 MB
__device__ unsigned char g_lh_l[BB * NN * TT * 2];        // 4 MB
__device__ unsigned char g_rh_h[BB * NN * TT * 2];        // 4 MB
__device__ unsigned char g_rh_l[BB * NN * TT * 2];        // 4 MB
// int8 GEMM operand blocks: 16 KB = [h 8K][l 8K], swizzle chunk^(row&3)
__device__ __align__(128) unsigned char g_Vq[8 * 16 * 16384];                 // 2 MB
__device__ __align__(128) unsigned char g_Gq[(size_t)BB * 8 * 16 * 16384];    // 64 MB
__device__ float         g_bsT[NN * NN];                  // 4 MB
__device__ float         g_part[8][BB * NN];              // 1 MB
__device__ float         g_cinv[BB * NN];
__device__ unsigned int  g_vmax_u = 0u;                   // static init (idempotent)

// ---------------- helpers -----------------------------------------------------
__device__ __forceinline__ uint32_t smem_u32(const void* p) {
    uint32_t a;
    asm("{ .reg .u64 t; cvta.to.shared.u64 t, %1; cvt.u32.u64 %0, t; }"
        : "=r"(a) : "l"(p));
    return a;
}
__device__ __forceinline__ void bulk_g2s(uint32_t dst, const void* src,
                                         uint32_t bytes, uint32_t mbar) {
    asm volatile(
        "cp.async.bulk.shared::cluster.global.mbarrier::complete_tx::bytes "
        "[%0], [%1], %2, [%3];"
        :: "r"(dst), "l"(src), "r"(bytes), "r"(mbar) : "memory");
}
__device__ __forceinline__ void mbar_init(uint32_t a, uint32_t n) {
    asm volatile("mbarrier.init.shared.b64 [%0], %1;" :: "r"(a), "r"(n) : "memory");
}
__device__ __forceinline__ void mbar_expect(uint32_t a, uint32_t tx) {
    asm volatile("mbarrier.arrive.expect_tx.shared.b64 _, [%0], %1;"
                 :: "r"(a), "r"(tx) : "memory");
}
__device__ __forceinline__ void mbar_arrive(uint32_t a) {
    asm volatile("mbarrier.arrive.shared.b64 _, [%0];" :: "r"(a) : "memory");
}
#define MBAR_WAIT(mbar, parity) do {                                            \
    uint32_t _m = (mbar), _p = (parity), _done;                                 \
    asm volatile("{\n\t.reg .pred p;\n\t"                                       \
        "mbarrier.try_wait.parity.acquire.cta.shared::cta.b64 p, [%1], %2;\n\t" \
        "selp.b32 %0, 1, 0, p;\n\t}" : "=r"(_done) : "r"(_m), "r"(_p) : "memory"); \
    if (!_done) {                                                               \
        asm volatile("{\n\t.reg .pred P1;\n\t"                                  \
        "WAIT_LOOP_%=:\n\t"                                                     \
        "mbarrier.try_wait.parity.acquire.cta.shared::cta.b64 P1, [%0], %1;\n\t" \
        "@P1 bra.uni WAIT_DONE_%=;\n\tbra.uni WAIT_LOOP_%=;\n\tWAIT_DONE_%=:\n\t}" \
        :: "r"(_m), "r"(_p) : "memory");                                        \
    }                                                                           \
} while (0)

#define LDSM_X4(r0, r1, r2, r3, addr)                                           \
    asm volatile("ldmatrix.sync.aligned.m8n8.x4.shared.b16 {%0,%1,%2,%3}, [%4];" \
        : "=r"(r0), "=r"(r1), "=r"(r2), "=r"(r3) : "r"(addr))

__device__ __forceinline__ void mma16816(float* d, const uint32_t* a,
                                         uint32_t b0, uint32_t b1) {
    asm volatile(
        "mma.sync.aligned.m16n8k16.row.col.f32.bf16.bf16.f32 "
        "{%0,%1,%2,%3}, {%4,%5,%6,%7}, {%8,%9}, {%0,%1,%2,%3};"
        : "+f"(d[0]), "+f"(d[1]), "+f"(d[2]), "+f"(d[3])
        : "r"(a[0]), "r"(a[1]), "r"(a[2]), "r"(a[3]), "r"(b0), "r"(b1));
}
#define IMMA(d, a, b0, b1)                                                      \
    asm volatile(                                                               \
        "mma.sync.aligned.m16n8k32.row.col.s32.s8.u8.s32 "                      \
        "{%0,%1,%2,%3}, {%4,%5,%6,%7}, {%8,%9}, {%0,%1,%2,%3};"                 \
        : "+r"((d)[0]), "+r"((d)[1]), "+r"((d)[2]), "+r"((d)[3])                \
        : "r"((a)[0]), "r"((a)[1]), "r"((a)[2]), "r"((a)[3]), "r"(b0), "r"(b1))

// =============================================================================
// Kernel 1: prep — HBM-bound; writes bf16 hi/lo splits PRE-SWIZZLED tile-major
// =============================================================================
__global__ __launch_bounds__(64) void prep_kernel(
    const float* __restrict__ x, const float* __restrict__ W1,
    const float* __restrict__ W2, const float* __restrict__ W3)
{
    __shared__ float sx[64][65];
    __shared__ float l1[64];
    __shared__ float sW1[64], sW3[64];

    const int t = threadIdx.x;
    sW1[t] = W1[t];
    sW3[t] = W3[t];

    const float4* x4 = reinterpret_cast<const float4*>(x) + (size_t)blockIdx.x * 1024;
#pragma unroll
    for (int i = 0; i < 16; i++) {
        int idx = i * 64 + t;
        float4 v = x4[idx];
        int f = idx >> 4;
        int c = (idx & 15) * 4;
        sx[f][c + 0] = v.x; sx[f][c + 1] = v.y;
        sx[f][c + 2] = v.z; sx[f][c + 3] = v.w;
    }
    __syncthreads();

    float acc = 0.f;
#pragma unroll
    for (int k = 0; k < 64; k++) acc += sx[t][k] * sW1[k];
    l1[t] = acc;

    float r = 0.f;
#pragma unroll
    for (int f = 0; f < 64; f++) r += sW3[f] * sx[f][t];

    __syncthreads();

    float l = 0.f;
#pragma unroll
    for (int f = 0; f < 64; f++) l += l1[f] * W2[f * 64 + t];

    const int b = blockIdx.x >> 10;
    const int n = blockIdx.x & 1023;
    const int row = n & 127;
    size_t blk = ((size_t)(b * 8 + (n >> 7))) * 16384u;
    uint32_t off = row * 128 + ((((t >> 3)) ^ (row & 7)) * 16) + (t & 7) * 2;

    __nv_bfloat16 lh = __float2bfloat16(l);
    __nv_bfloat16 rh = __float2bfloat16(r);
    *(__nv_bfloat16*)&g_lh_h[blk + off] = lh;
    *(__nv_bfloat16*)&g_lh_l[blk + off] = __float2bfloat16(l - __bfloat162float(lh));
    *(__nv_bfloat16*)&g_rh_h[blk + off] = rh;
    *(__nv_bfloat16*)&g_rh_l[blk + off] = __float2bfloat16(r - __bfloat162float(rh));
}

// =============================================================================
// Kernel 2: Vmax (deterministic) + quantize Vs into tile-major swizzled blocks
// =============================================================================
__global__ __launch_bounds__(256) void vmax_kernel(const float* __restrict__ Vs)
{
    int i = (blockIdx.x * 256 + threadIdx.x) * 4;
    float4 v = *(const float4*)&Vs[i];
    float m = fmaxf(fmaxf(fabsf(v.x), fabsf(v.y)), fmaxf(fabsf(v.z), fabsf(v.w)));
#pragma unroll
    for (int s = 16; s > 0; s >>= 1)
        m = fmaxf(m, __shfl_xor_sync(0xffffffffu, m, s));
    if ((threadIdx.x & 31) == 0)
        atomicMax(&g_vmax_u, __float_as_uint(m));
}

__global__ __launch_bounds__(256) void quant_vs(const float* __restrict__ Vs)
{
    const float vmax = __uint_as_float(g_vmax_u);
    const float inv_s = 32639.f / fmaxf(vmax, 1e-30f);
    int e = (blockIdx.x * 256 + threadIdx.x) * 4;
    float4 v = *(const float4*)&Vs[e];
    uint32_t hp = 0, lp = 0;
    float vv[4] = {v.x, v.y, v.z, v.w};
#pragma unroll
    for (int j = 0; j < 4; j++) {
        int q = __float2int_rn(vv[j] * inv_s);
        q = max(-32768, min(32639, q));
        int vl = ((q + 128) & 255) - 128;
        int vh = (q - vl) >> 8;
        hp |= ((uint32_t)(vh & 255)) << (j * 8);
        lp |= ((uint32_t)(vl & 255)) << (j * 8);
    }
    int i = e >> 10;
    int k = e & 1023;
    int itile = i >> 7, row = i & 127;
    int kk = k >> 6, kc = k & 63;
    int c = kc >> 4, byt = kc & 15;
    uint32_t blk = (uint32_t)(itile * 16 + kk) * 16384u;
    uint32_t off = blk + row * 64 + (((c ^ (row & 3))) * 16) + byt;
    *(uint32_t*)&g_Vq[off] = hp;
    *(uint32_t*)&g_Vq[off + 8192] = lp;
}

// =============================================================================
// Kernel 2d: transpose bias once
// =============================================================================
__global__ __launch_bounds__(256) void transpose_bs(const float* __restrict__ bs)
{
    __shared__ float t[32][33];
    const int tx = threadIdx.x, ty = threadIdx.y;
    const int x0 = blockIdx.x * 32, y0 = blockIdx.y * 32;
#pragma unroll
    for (int r = 0; r < 4; r++)
        t[ty + r * 8][tx] = bs[(size_t)(y0 + ty + r * 8) * NN + x0 + tx];
    __syncthreads();
#pragma unroll
    for (int r = 0; r < 4; r++)
        g_bsT[(size_t)(x0 + ty + r * 8) * NN + y0 + tx] = t[tx][ty + r * 8];
}

// =============================================================================
// Kernel 3: product via bf16 mma. A resident + 4 B-tiles via bulk copies.
// (R14 structure: epilogue, then sync, then refill.)
// =============================================================================
#define PM_SMEM 98304

__global__ void __launch_bounds__(256, 2) product_mma()
{
    extern __shared__ __align__(1024) char dsm[];
    __shared__ __align__(8) ull pm_mbars[3];   // [A][Bslot0][Bslot1]
    const uint32_t sm0 = smem_u32(dsm);
    const uint32_t mbA = smem_u32(pm_mbars);

    const int tid  = threadIdx.x;
    const int lane = tid & 31;
    const int w    = tid >> 5;
    const int b    = blockIdx.z;
    const int m0   = blockIdx.y * 128;
    const int mtile = blockIdx.y;
    const int ng0  = blockIdx.x * 512;
    const int nt0  = blockIdx.x * 4;           // base ntile

    const int wi0 = (w >> 1) * 32;
    const int wm0 = (w & 1) * 64;

    const int a_row  = wi0 + (lane & 15);
    const int a_half = lane >> 4;
    const int b_nB   = (lane & 7) + ((lane >> 4) << 3);
    const int b_half = (lane >> 3) & 1;
    const int swz    = lane & 7;

    if (tid == 0) {
        mbar_init(mbA, 1);
        mbar_init(mbA + 8, 1);
        mbar_init(mbA + 16, 1);
    }
    __syncthreads();

    auto issue_B = [&](int t) {
        uint32_t mb = mbA + 8 + (t & 1) * 8;
        uint32_t sb = sm0 + 32768 + (t & 1) * 32768;
        size_t blk = ((size_t)(b * 8 + nt0 + t)) * 16384u;
        mbar_expect(mb, 32768);
        bulk_g2s(sb,         g_lh_h + blk, 16384, mb);
        bulk_g2s(sb + 16384, g_lh_l + blk, 16384, mb);
    };

    if (tid == 0) {
        size_t ablk = ((size_t)(b * 8 + mtile)) * 16384u;
        mbar_expect(mbA, 32768);
        bulk_g2s(sm0,         g_rh_h + ablk, 16384, mbA);
        bulk_g2s(sm0 + 16384, g_rh_l + ablk, 16384, mbA);
        issue_B(0);
        issue_B(1);
    }

#pragma unroll 1
    for (int t = 0; t < 4; t++) {
        if (t == 0) MBAR_WAIT(mbA, 0);
        MBAR_WAIT(mbA + 8 + (t & 1) * 8, (t >> 1) & 1);

        const uint32_t sbB = sm0 + 32768 + (t & 1) * 32768;

        float acc[2][8][4];
#pragma unroll
        for (int mt = 0; mt < 2; mt++)
#pragma unroll
            for (int j = 0; j < 8; j++)
#pragma unroll
                for (int q = 0; q < 4; q++) acc[mt][j][q] = 0.f;

#pragma unroll
        for (int ks = 0; ks < 4; ks++) {
            uint32_t ah[2][4], al[2][4];
#pragma unroll
            for (int mt = 0; mt < 2; mt++) {
                uint32_t off = (a_row + mt * 16) * 128 + (((2 * ks + a_half) ^ swz) * 16);
                LDSM_X4(ah[mt][0], ah[mt][1], ah[mt][2], ah[mt][3], sm0 + off);
                LDSM_X4(al[mt][0], al[mt][1], al[mt][2], al[mt][3], sm0 + 16384 + off);
            }
#pragma unroll
            for (int nt = 0; nt < 4; nt++) {
                uint32_t bh[4], bl[4];
                uint32_t off = (wm0 + nt * 16 + b_nB) * 128 + (((2 * ks + b_half) ^ swz) * 16);
                LDSM_X4(bh[0], bh[1], bh[2], bh[3], sbB + off);
                LDSM_X4(bl[0], bl[1], bl[2], bl[3], sbB + 16384 + off);
#pragma unroll
                for (int mt = 0; mt < 2; mt++) {
                    mma16816(acc[mt][nt * 2 + 0], ah[mt], bh[0], bh[1]);
                    mma16816(acc[mt][nt * 2 + 1], ah[mt], bh[2], bh[3]);
                    mma16816(acc[mt][nt * 2 + 0], ah[mt], bl[0], bl[1]);
                    mma16816(acc[mt][nt * 2 + 1], ah[mt], bl[2], bl[3]);
                    mma16816(acc[mt][nt * 2 + 0], al[mt], bh[0], bh[1]);
                    mma16816(acc[mt][nt * 2 + 1], al[mt], bh[2], bh[3]);
                }
            }
        }

        // epilogue: sigmoid, 16-bit quantize, write into swizzled Gq
        const int n0t = ng0 + t * 128;
#pragma unroll
        for (int mt = 0; mt < 2; mt++) {
            int r0 = m0 + wi0 + mt * 16 + (lane >> 2);
#pragma unroll
            for (int nt = 0; nt < 4; nt++)
#pragma unroll
                for (int h = 0; h < 2; h++) {
                    int j = nt * 2 + h;
                    int cn = n0t + wm0 + nt * 16 + h * 8 + (lane & 3) * 2;
                    int kk = cn >> 6, kc = cn & 63;
                    int c = kc >> 4, byt = kc & 15;
#pragma unroll
                    for (int rr = 0; rr < 2; rr++) {
                        int row = r0 + rr * 8;
                        int rowt = row & 127;
                        float p0 = acc[mt][j][rr * 2 + 0];
                        float p1 = acc[mt][j][rr * 2 + 1];
                        float2 bb = *(const float2*)&g_bsT[(size_t)row * NN + cn];
                        float g0 = 1.f / (1.f + __expf(-(p0 + bb.x)));
                        float g1 = 1.f / (1.f + __expf(-(p1 + bb.y)));
                        uint32_t q0 = __float2uint_rn(g0 * 65535.f);
                        uint32_t q1 = __float2uint_rn(g1 * 65535.f);
                        size_t blk = ((size_t)((b * 8 + mtile) * 16 + kk)) * 16384u;
                        size_t off = blk + rowt * 64 + (((c ^ (rowt & 3))) * 16) + byt;
                        *(unsigned short*)&g_Gq[off] =
                            (unsigned short)((q0 >> 8) | ((q1 >> 8) << 8));
                        *(unsigned short*)&g_Gq[off + 8192] =
                            (unsigned short)((q0 & 255) | ((q1 & 255) << 8));
                    }
                }
        }

        __syncthreads();
        if (tid == 0 && t + 2 < 4) issue_B(t + 2);
    }
}

// =============================================================================
// Kernel 4: int8 tensor-core GEMM (256 threads, warp tile 32x64), bulk-copy
// producer, barrier-free (full tx + empty 256-arrival mbarriers).
// ONE change vs R14-best: 6-stage ring (192 KB) for straggler slack.
// =============================================================================
#define GI_STAGE_BYTES 32768
#define GI_STAGES 6
#define GI_SMEM (GI_STAGES * GI_STAGE_BYTES)   // 192 KB

__global__ void __launch_bounds__(256, 1) gemm_i8(float* __restrict__ S)
{
    extern __shared__ __align__(1024) char dsm[];
    __shared__ __align__(8) ull mbars[2 * GI_STAGES];    // [full x6][empty x6]
    __shared__ float wsum[8][64];
    const uint32_t sm0 = smem_u32(dsm);
    const uint32_t mbF = smem_u32(mbars);
    const uint32_t mbE = mbF + GI_STAGES * 8;

    const int tid  = threadIdx.x;
    const int lane = tid & 31;
    const int w    = tid >> 5;
    const int b    = blockIdx.z;
    const int itile = blockIdx.y;
    const int mtile = blockIdx.x;
    const int i0g  = itile * 128;
    const int m0   = mtile * 128;

    const int wi0 = (w >> 1) * 32;
    const int wm0 = (w & 1) * 64;

    const int a_row  = wi0 + (lane & 15);
    const int a_half = lane >> 4;
    const int aswz   = a_row & 3;
    const int b_nB   = (lane & 7) + ((lane >> 4) << 3);
    const int b_half = (lane >> 3) & 1;
    const int bswz   = b_nB & 3;

    if (tid == 0) {
#pragma unroll
        for (int s = 0; s < GI_STAGES; s++) {
            mbar_init(mbF + s * 8, 1);
            mbar_init(mbE + s * 8, 256);
        }
    }
    __syncthreads();

    const unsigned char* srcA0 = g_Vq + (size_t)(itile * 16) * 16384u;
    const unsigned char* srcB0 = g_Gq + (size_t)((b * 8 + mtile) * 16) * 16384u;

    auto issue = [&](int kk, int s) {
        uint32_t mb = mbF + s * 8;
        uint32_t sb = sm0 + s * GI_STAGE_BYTES;
        mbar_expect(mb, 32768);
        bulk_g2s(sb,         srcA0 + (size_t)kk * 16384u, 16384, mb);
        bulk_g2s(sb + 16384, srcB0 + (size_t)kk * 16384u, 16384, mb);
    };

    if (tid == 0) {
#pragma unroll
        for (int k = 0; k < GI_STAGES; k++) issue(k, k);
    }

    int acc1[2][8][4], acc2[2][8][4];
#pragma unroll
    for (int mt = 0; mt < 2; mt++)
#pragma unroll
        for (int j = 0; j < 8; j++)
#pragma unroll
            for (int q = 0; q < 4; q++) { acc1[mt][j][q] = 0; acc2[mt][j][q] = 0; }

    int s = 0, ph = 0;
#pragma unroll 1
    for (int kk = 0; kk < 16; kk++) {
        MBAR_WAIT(mbF + s * 8, ph);

        const uint32_t sb = sm0 + s * GI_STAGE_BYTES;

#pragma unroll
        for (int ks = 0; ks < 2; ks++) {
            uint32_t ah[2][4], al[2][4];
#pragma unroll
            for (int mt = 0; mt < 2; mt++) {
                uint32_t off = (a_row + mt * 16) * 64
                             + (((2 * ks + a_half) ^ aswz) * 16);
                LDSM_X4(ah[mt][0], ah[mt][1], ah[mt][2], ah[mt][3], sb + off);
                LDSM_X4(al[mt][0], al[mt][1], al[mt][2], al[mt][3], sb + 8192 + off);
            }
            uint32_t bh[4][4], bl[4][4];
#pragma unroll
            for (int nt = 0; nt < 4; nt++) {
                uint32_t off = (wm0 + nt * 16 + b_nB) * 64
                             + (((2 * ks + b_half) ^ bswz) * 16);
                LDSM_X4(bh[nt][0], bh[nt][1], bh[nt][2], bh[nt][3], sb + 16384 + off);
                LDSM_X4(bl[nt][0], bl[nt][1], bl[nt][2], bl[nt][3], sb + 24576 + off);
            }
            // term-grouped issue (max RAW spacing on acc2)
#pragma unroll
            for (int mt = 0; mt < 2; mt++)
#pragma unroll
                for (int nt = 0; nt < 4; nt++) {
                    IMMA(acc1[mt][nt * 2 + 0], ah[mt], bh[nt][0], bh[nt][1]);
                    IMMA(acc1[mt][nt * 2 + 1], ah[mt], bh[nt][2], bh[nt][3]);
                }
#pragma unroll
            for (int mt = 0; mt < 2; mt++)
#pragma unroll
                for (int nt = 0; nt < 4; nt++) {
                    IMMA(acc2[mt][nt * 2 + 0], ah[mt], bl[nt][0], bl[nt][1]);
                    IMMA(acc2[mt][nt * 2 + 1], ah[mt], bl[nt][2], bl[nt][3]);
                }
#pragma unroll
            for (int mt = 0; mt < 2; mt++)
#pragma unroll
                for (int nt = 0; nt < 4; nt++) {
                    IMMA(acc2[mt][nt * 2 + 0], al[mt], bh[nt][0], bh[nt][1]);
                    IMMA(acc2[mt][nt * 2 + 1], al[mt], bh[nt][2], bh[nt][3]);
                }
        }

        // all fragment reads for stage kk are complete (LDSM is synchronous)
        mbar_arrive(mbE + s * 8);
        if (tid == 0 && kk + GI_STAGES < 16) {
            MBAR_WAIT(mbE + s * 8, ph);   // all 256 consumed this slot's phase
            issue(kk + GI_STAGES, s);     // refill the just-released slot
        }
        if (++s == GI_STAGES) { s = 0; ph ^= 1; }
    }

    // epilogue: S = sc1*acc1 + sc2*acc2; write exp(S) + column partials
    const float s_scale = __uint_as_float(g_vmax_u) * (1.f / 32639.f);
    const float base = s_scale * (1.f / 65535.f);
    const float sc1 = base * 65536.f;
    const float sc2 = base * 256.f;

    float cs[16];
#pragma unroll
    for (int i = 0; i < 16; i++) cs[i] = 0.f;

    float* Sb = S + ((size_t)b << 20);
#pragma unroll
    for (int mt = 0; mt < 2; mt++) {
        int r0 = i0g + wi0 + mt * 16 + (lane >> 2);
#pragma unroll
        for (int nt = 0; nt < 4; nt++)
#pragma unroll
            for (int h = 0; h < 2; h++) {
                int j = nt * 2 + h;
                int cm = m0 + wm0 + nt * 16 + h * 8 + (lane & 3) * 2;
                float v0 = fmaf(sc1, (float)acc1[mt][j][0], sc2 * (float)acc2[mt][j][0]);
                float v1 = fmaf(sc1, (float)acc1[mt][j][1], sc2 * (float)acc2[mt][j][1]);
                float v2 = fmaf(sc1, (float)acc1[mt][j][2], sc2 * (float)acc2[mt][j][2]);
                float v3 = fmaf(sc1, (float)acc1[mt][j][3], sc2 * (float)acc2[mt][j][3]);
                float e0 = __expf(v0), e1 = __expf(v1);
                float e2 = __expf(v2), e3 = __expf(v3);
                *(float2*)&Sb[((size_t)r0 << 10) + cm] = make_float2(e0, e1);
                *(float2*)&Sb[((size_t)(r0 + 8) << 10) + cm] = make_float2(e2, e3);
                cs[nt * 4 + h * 2 + 0] += e0 + e2;
                cs[nt * 4 + h * 2 + 1] += e1 + e3;
            }
    }
#pragma unroll
    for (int i = 0; i < 16; i++) {
        cs[i] += __shfl_xor_sync(0xffffffffu, cs[i], 4);
        cs[i] += __shfl_xor_sync(0xffffffffu, cs[i], 8);
        cs[i] += __shfl_xor_sync(0xffffffffu, cs[i], 16);
    }
    if (lane < 4) {
#pragma unroll
        for (int nt = 0; nt < 4; nt++)
#pragma unroll
            for (int h = 0; h < 2; h++) {
                wsum[w][nt * 16 + h * 8 + lane * 2 + 0] = cs[nt * 4 + h * 2 + 0];
                wsum[w][nt * 16 + h * 8 + lane * 2 + 1] = cs[nt * 4 + h * 2 + 1];
            }
    }
    __syncthreads();
    if (tid < 128) {
        int h = tid >> 6, c = tid & 63;
        float sum = wsum[h][c] + wsum[2 + h][c] + wsum[4 + h][c] + wsum[6 + h][c];
        g_part[itile][((size_t)b << 10) + m0 + h * 64 + c] = sum;
    }
}

// =============================================================================
// Kernel 5: reduce per-i-tile partials -> 1/colsum
// =============================================================================
__global__ __launch_bounds__(256) void reduce_part()
{
    int t = blockIdx.x * 256 + threadIdx.x;
    float s = 0.f;
#pragma unroll
    for (int q = 0; q < 8; q++) s += g_part[q][t];
    g_cinv[t] = __fdividef(1.f, s);
}

// =============================================================================
// Kernel 6: normalize in place: out = expS * (1/colsum)
// =============================================================================
__global__ __launch_bounds__(256) void normalize_kernel(float* __restrict__ S)
{
    const int bi = blockIdx.x;
    const int b = bi >> 10;
    const int m = threadIdx.x * 4;
    size_t base = (size_t)bi * NN + m;

    float4 v  = *(const float4*)&S[base];
    float4 iv = *(const float4*)&g_cinv[b * NN + m];
    float4 o;
    o.x = v.x * iv.x;
    o.y = v.y * iv.y;
    o.z = v.z * iv.z;
    o.w = v.w * iv.w;
    *(float4*)&S[base] = o;
}

// =============================================================================
extern "C" void kernel_launch(void* const* d_in, const int* in_sizes, int n_in,
                              void* d_out, int out_size)
{
    (void)in_sizes; (void)n_in; (void)out_size;
    const float* x  = (const float*)d_in[0];
    const float* W1 = (const float*)d_in[1];
    const float* W2 = (const float*)d_in[2];
    const float* W3 = (const float*)d_in[3];
    const float* bs = (const float*)d_in[4];
    const float* Vs = (const float*)d_in[5];
    float* out = (float*)d_out;

    cudaFuncSetAttribute(product_mma, cudaFuncAttributeMaxDynamicSharedMemorySize,
                         PM_SMEM);
    cudaFuncSetAttribute(gemm_i8, cudaFuncAttributeMaxDynamicSharedMemorySize,
                         GI_SMEM);

    prep_kernel<<<BB * NN, 64>>>(x, W1, W2, W3);
    vmax_kernel<<<NN * NN / 1024, 256>>>(Vs);
    quant_vs<<<NN * NN / 1024, 256>>>(Vs);
    transpose_bs<<<dim3(32, 32), dim3(32, 8)>>>(bs);
    product_mma<<<dim3(2, 8, BB), 256, PM_SMEM>>>();
    gemm_i8<<<dim3(8, 8, BB), 256, GI_SMEM>>>(out);
    reduce_part<<<128, 256>>>();
    normalize_kernel<<<BB * NN, 256>>>(out);
}